// round 1
// baseline (speedup 1.0000x reference)
#include <cuda_runtime.h>
#include <math.h>

#define Bn   4096
#define DIN  1856
#define Hn   128
#define HBW  256
#define BAND 513          // 2*HBW+1
#define DT   0.25f

// -------- device scratch (static: no allocations allowed) --------
__device__ float g_adj [Bn * BAND];   // banded, row-normalized adjacency
__device__ float g_h   [Bn * Hn];     // current ODE state
__device__ float g_hn  [Bn * Hn];     // neighbor aggregation
__device__ float g_htmp[Bn * Hn];     // RK4 intermediate state
__device__ float g_acc [Bn * Hn];     // RK4 accumulator

// ================= adjacency build (banded + row-normalized) =================
__global__ __launch_bounds__(256) void build_adj_kernel(
        const int* __restrict__ spk, const float* __restrict__ mm)
{
    int i = blockIdx.x;
    int t = threadIdx.x;
    __shared__ float red[256];

    int   si  = spk[i];
    float mi0 = mm[3*i+0], mi1 = mm[3*i+1], mi2 = mm[3*i+2];

    float v[3];
    int   cnt = 0;
    float lsum = 0.f;
    for (int off = t; off < BAND; off += 256) {
        int j = i + off - HBW;
        float val = 0.f;
        if (j >= 0 && j < Bn) {
            if (j == i) {
                val = 1.0f;
            } else {
                float d   = fabsf((float)(off - HBW));
                float tem = expf(-0.1f * d);
                if (spk[j] == si) {
                    val = 0.8f * tem;
                } else {
                    float md = (fabsf(mi0 - mm[3*j+0]) +
                                fabsf(mi1 - mm[3*j+1]) +
                                fabsf(mi2 - mm[3*j+2])) * (1.0f/3.0f);
                    val = 0.5f * tem * (1.0f - md);
                }
            }
        }
        v[cnt++] = val;
        lsum += val;
    }

    red[t] = lsum;
    __syncthreads();
    for (int s = 128; s > 0; s >>= 1) {
        if (t < s) red[t] += red[t + s];
        __syncthreads();
    }
    float inv = 1.0f / (red[0] + 1e-8f);

    cnt = 0;
    for (int off = t; off < BAND; off += 256)
        g_adj[(size_t)i * BAND + off] = v[cnt++] * inv;
}

// ================= input projection: g_h = X @ Wp + bp =================
// BM=16 rows/block, 128 threads, 4x4 register tile, BK=32
__global__ __launch_bounds__(128) void proj_kernel(
        const float* __restrict__ X, const float* __restrict__ Wp,
        const float* __restrict__ bp)
{
    __shared__ float  fs[16][32];
    __shared__ float4 ws[32][32];

    int t  = threadIdx.x;
    int tx = t & 31, ty = t >> 5;           // ty 0..3
    int i0 = blockIdx.x * 16;
    int r0 = ty * 4;

    float acc[4][4] = {};

    for (int cb = 0; cb < DIN/32; cb++) {
        int kb = cb * 32;
        #pragma unroll
        for (int l = 0; l < 4; l++) {       // 512 floats of X tile
            int lin = t + l * 128;
            int r = lin >> 5, kk = lin & 31;
            fs[r][kk] = X[(size_t)(i0 + r) * DIN + kb + kk];
        }
        #pragma unroll
        for (int l = 0; l < 8; l++) {       // 1024 float4 of Wp tile
            int lin = t + l * 128;
            int kk = lin >> 5, c4 = lin & 31;
            ws[kk][c4] = *(const float4*)&Wp[(size_t)(kb + kk) * Hn + c4 * 4];
        }
        __syncthreads();
        #pragma unroll
        for (int kk = 0; kk < 32; kk++) {
            float4 b = ws[kk][tx];
            #pragma unroll
            for (int r = 0; r < 4; r++) {
                float a = fs[r0 + r][kk];
                acc[r][0] += a * b.x; acc[r][1] += a * b.y;
                acc[r][2] += a * b.z; acc[r][3] += a * b.w;
            }
        }
        __syncthreads();
    }

    float4 bv = *(const float4*)&bp[tx * 4];
    #pragma unroll
    for (int r = 0; r < 4; r++) {
        float4 o = make_float4(acc[r][0] + bv.x, acc[r][1] + bv.y,
                               acc[r][2] + bv.z, acc[r][3] + bv.w);
        *(float4*)&g_h[(size_t)(i0 + r0 + r) * Hn + tx * 4] = o;
    }
}

// ================= banded matvec: g_hn = adjB @ x =================
__global__ __launch_bounds__(128) void bandmv_kernel(int x_is_htmp)
{
    const float* __restrict__ x = x_is_htmp ? g_htmp : g_h;
    __shared__ float  adjS[16][32];
    __shared__ float4 xs[32][32];

    int t  = threadIdx.x;
    int tx = t & 31, ty = t >> 5;
    int i0 = blockIdx.x * 16;
    int r0 = ty * 4;

    float acc[4][4] = {};

    for (int cb = 0; cb < 17; cb++) {       // j in [i0-256, i0+287]
        int jbase = i0 - HBW + cb * 32;
        #pragma unroll
        for (int l = 0; l < 8; l++) {       // x tile: 32 rows x 128 cols
            int lin = t + l * 128;
            int jj = lin >> 5, c4 = lin & 31;
            int j = jbase + jj;
            float4 v = make_float4(0.f, 0.f, 0.f, 0.f);
            if (j >= 0 && j < Bn)
                v = *(const float4*)&x[(size_t)j * Hn + c4 * 4];
            xs[jj][c4] = v;
        }
        #pragma unroll
        for (int l = 0; l < 4; l++) {       // adj tile 16x32
            int lin = t + l * 128;
            int r = lin >> 5, jj = lin & 31;
            int off = cb * 32 + jj - r;     // = j - i + HBW
            int j = jbase + jj;
            float v = 0.f;
            if (off >= 0 && off < BAND && j >= 0 && j < Bn)
                v = g_adj[(size_t)(i0 + r) * BAND + off];
            adjS[r][jj] = v;
        }
        __syncthreads();
        #pragma unroll
        for (int jj = 0; jj < 32; jj++) {
            float4 b = xs[jj][tx];
            #pragma unroll
            for (int r = 0; r < 4; r++) {
                float a = adjS[r0 + r][jj];
                acc[r][0] += a * b.x; acc[r][1] += a * b.y;
                acc[r][2] += a * b.z; acc[r][3] += a * b.w;
            }
        }
        __syncthreads();
    }

    #pragma unroll
    for (int r = 0; r < 4; r++) {
        float4 o = make_float4(acc[r][0], acc[r][1], acc[r][2], acc[r][3]);
        *(float4*)&g_hn[(size_t)(i0 + r0 + r) * Hn + tx * 4] = o;
    }
}

// ====== fused MLP + RK4 epilogue:
//   z = tanh(x@W1a + hn@W1b + b1);  k = z@W2 + b2
//   mode 0: acc = h + (DT/6)k;  htmp = h + (DT/2)k
//   mode 1: acc += (DT/3)k;     htmp = h + (DT/2)k
//   mode 2: acc += (DT/3)k;     htmp = h +  DT  k
//   mode 3: hout = acc + (DT/6)k      (hout = g_h, or d_out on last step)
__global__ __launch_bounds__(128) void mlp_kernel(
        int x_is_htmp, int mode, float* __restrict__ dout, int to_dout,
        const float* __restrict__ W1, const float* __restrict__ b1,
        const float* __restrict__ W2, const float* __restrict__ b2)
{
    const float* __restrict__ x = x_is_htmp ? g_htmp : g_h;
    __shared__ __align__(16) float xsh [16 * 128];
    __shared__ __align__(16) float hnsh[16 * 128];
    __shared__ __align__(16) float zsh [16 * 128];

    int t  = threadIdx.x;
    int tx = t & 31, ty = t >> 5;
    int i0 = blockIdx.x * 16;
    int r0 = ty * 4;

    #pragma unroll
    for (int l = 0; l < 4; l++) {
        int lin = t + l * 128;
        ((float4*)xsh )[lin] = *(const float4*)&x   [(size_t)i0 * Hn + lin * 4];
        ((float4*)hnsh)[lin] = *(const float4*)&g_hn[(size_t)i0 * Hn + lin * 4];
    }
    __syncthreads();

    // ---- layer 1: z = tanh([x,hn] @ W1 + b1) ----
    float4 b1v = *(const float4*)&b1[tx * 4];
    float az[4][4];
    #pragma unroll
    for (int r = 0; r < 4; r++) {
        az[r][0] = b1v.x; az[r][1] = b1v.y; az[r][2] = b1v.z; az[r][3] = b1v.w;
    }
    #pragma unroll 8
    for (int kk = 0; kk < Hn; kk++) {
        float4 wt = *(const float4*)&W1[(size_t) kk       * Hn + tx * 4];
        float4 wb = *(const float4*)&W1[(size_t)(Hn + kk) * Hn + tx * 4];
        #pragma unroll
        for (int r = 0; r < 4; r++) {
            float xv = xsh [(r0 + r) * 128 + kk];
            float hv = hnsh[(r0 + r) * 128 + kk];
            az[r][0] += xv * wt.x + hv * wb.x;
            az[r][1] += xv * wt.y + hv * wb.y;
            az[r][2] += xv * wt.z + hv * wb.z;
            az[r][3] += xv * wt.w + hv * wb.w;
        }
    }
    #pragma unroll
    for (int r = 0; r < 4; r++) {
        float4 z = make_float4(tanhf(az[r][0]), tanhf(az[r][1]),
                               tanhf(az[r][2]), tanhf(az[r][3]));
        ((float4*)zsh)[(r0 + r) * 32 + tx] = z;
    }
    __syncthreads();

    // ---- layer 2: k = z @ W2 + b2 ----
    float4 b2v = *(const float4*)&b2[tx * 4];
    float ak[4][4];
    #pragma unroll
    for (int r = 0; r < 4; r++) {
        ak[r][0] = b2v.x; ak[r][1] = b2v.y; ak[r][2] = b2v.z; ak[r][3] = b2v.w;
    }
    #pragma unroll 8
    for (int kk = 0; kk < Hn; kk++) {
        float4 w2 = *(const float4*)&W2[(size_t)kk * Hn + tx * 4];
        #pragma unroll
        for (int r = 0; r < 4; r++) {
            float zv = zsh[(r0 + r) * 128 + kk];
            ak[r][0] += zv * w2.x; ak[r][1] += zv * w2.y;
            ak[r][2] += zv * w2.z; ak[r][3] += zv * w2.w;
        }
    }

    // ---- fused RK4 epilogue ----
    const float cA6 = DT / 6.0f, cA3 = DT / 3.0f, cH2 = DT * 0.5f;
    #pragma unroll
    for (int r = 0; r < 4; r++) {
        size_t g = (size_t)(i0 + r0 + r) * Hn + tx * 4;
        float4 k = make_float4(ak[r][0], ak[r][1], ak[r][2], ak[r][3]);
        if (mode == 0) {
            float4 hv = *(const float4*)&g_h[g];
            *(float4*)&g_acc[g]  = make_float4(hv.x + cA6*k.x, hv.y + cA6*k.y,
                                               hv.z + cA6*k.z, hv.w + cA6*k.w);
            *(float4*)&g_htmp[g] = make_float4(hv.x + cH2*k.x, hv.y + cH2*k.y,
                                               hv.z + cH2*k.z, hv.w + cH2*k.w);
        } else if (mode == 3) {
            float4 av = *(const float4*)&g_acc[g];
            float4 o = make_float4(av.x + cA6*k.x, av.y + cA6*k.y,
                                   av.z + cA6*k.z, av.w + cA6*k.w);
            if (to_dout) *(float4*)&dout[g] = o;
            else         *(float4*)&g_h[g]  = o;
        } else {
            float ct = (mode == 2) ? DT : cH2;
            float4 av = *(const float4*)&g_acc[g];
            *(float4*)&g_acc[g] = make_float4(av.x + cA3*k.x, av.y + cA3*k.y,
                                              av.z + cA3*k.z, av.w + cA3*k.w);
            float4 hv = *(const float4*)&g_h[g];
            *(float4*)&g_htmp[g] = make_float4(hv.x + ct*k.x, hv.y + ct*k.y,
                                               hv.z + ct*k.z, hv.w + ct*k.w);
        }
    }
}

// ================= launch =================
extern "C" void kernel_launch(void* const* d_in, const int* in_sizes, int n_in,
                              void* d_out, int out_size)
{
    const float* features = (const float*)d_in[0];
    const int*   spk      = (const int*)  d_in[1];
    const float* mm       = (const float*)d_in[2];
    const float* Wp       = (const float*)d_in[3];
    const float* bp       = (const float*)d_in[4];
    const float* W1       = (const float*)d_in[5];
    const float* b1       = (const float*)d_in[6];
    const float* W2       = (const float*)d_in[7];
    const float* b2       = (const float*)d_in[8];
    float* out = (float*)d_out;

    build_adj_kernel<<<Bn, 256>>>(spk, mm);
    proj_kernel<<<Bn/16, 128>>>(features, Wp, bp);

    for (int s = 0; s < 4; s++) {
        for (int e = 0; e < 4; e++) {
            bandmv_kernel<<<Bn/16, 128>>>(e > 0 ? 1 : 0);
            mlp_kernel<<<Bn/16, 128>>>(e > 0 ? 1 : 0, e, out,
                                       (s == 3 && e == 3) ? 1 : 0,
                                       W1, b1, W2, b2);
        }
    }
}

// round 3
// speedup vs baseline: 1.4331x; 1.4331x over previous
#include <cuda_runtime.h>
#include <math.h>

#define Bn   4096
#define DIN  1856
#define Hn   128
#define HBW  128
#define BAND 257          // 2*HBW+1
#define NJT  9            // ceil((8 + 2*HBW)/32) j-tiles per 8-row block
#define DT   0.25f

// -------- device scratch (static: no allocations allowed) --------
__device__ float g_adj [Bn * BAND];   // banded, row-normalized adjacency
__device__ float g_h   [Bn * Hn];     // current ODE state
__device__ float g_htmp[Bn * Hn];     // RK4 intermediate state
__device__ float g_acc [Bn * Hn];     // RK4 accumulator

// ================= adjacency build (banded + row-normalized) =================
__global__ __launch_bounds__(256) void build_adj_kernel(
        const int* __restrict__ spk, const float* __restrict__ mm)
{
    int i = blockIdx.x;
    int t = threadIdx.x;
    __shared__ float red[256];

    int   si  = spk[i];
    float mi0 = mm[3*i+0], mi1 = mm[3*i+1], mi2 = mm[3*i+2];

    float v[2];
    int   cnt = 0;
    float lsum = 0.f;
    for (int off = t; off < BAND; off += 256) {
        int j = i + off - HBW;
        float val = 0.f;
        if (j >= 0 && j < Bn) {
            if (j == i) {
                val = 1.0f;
            } else {
                float d   = fabsf((float)(off - HBW));
                float tem = expf(-0.1f * d);
                if (spk[j] == si) {
                    val = 0.8f * tem;
                } else {
                    float md = (fabsf(mi0 - mm[3*j+0]) +
                                fabsf(mi1 - mm[3*j+1]) +
                                fabsf(mi2 - mm[3*j+2])) * (1.0f/3.0f);
                    val = 0.5f * tem * (1.0f - md);
                }
            }
        }
        v[cnt++] = val;
        lsum += val;
    }

    red[t] = lsum;
    __syncthreads();
    for (int s = 128; s > 0; s >>= 1) {
        if (t < s) red[t] += red[t + s];
        __syncthreads();
    }
    float inv = 1.0f / (red[0] + 1e-8f);

    cnt = 0;
    for (int off = t; off < BAND; off += 256)
        g_adj[(size_t)i * BAND + off] = v[cnt++] * inv;
}

// ================= input projection: g_h = X @ Wp + bp =================
// BM=8 rows/block, 128 threads, 2x4 register tile, BK=32, grid=512
__global__ __launch_bounds__(128) void proj_kernel(
        const float* __restrict__ X, const float* __restrict__ Wp,
        const float* __restrict__ bp)
{
    __shared__ float  fs[8][32];
    __shared__ float4 ws[32][32];

    int t  = threadIdx.x;
    int tx = t & 31, ty = t >> 5;           // ty 0..3
    int i0 = blockIdx.x * 8;
    int r0 = ty * 2;                        // 2 rows per warp

    float acc[2][4] = {};

    for (int cb = 0; cb < DIN/32; cb++) {
        int kb = cb * 32;
        {   // 256 floats of X tile -> 2 per thread
            int lin = t;
            fs[lin >> 5][lin & 31] = X[(size_t)(i0 + (lin >> 5)) * DIN + kb + (lin & 31)];
            lin = t + 128;
            fs[lin >> 5][lin & 31] = X[(size_t)(i0 + (lin >> 5)) * DIN + kb + (lin & 31)];
        }
        #pragma unroll
        for (int l = 0; l < 8; l++) {       // 1024 float4 of Wp tile
            int lin = t + l * 128;
            int kk = lin >> 5, c4 = lin & 31;
            ws[kk][c4] = *(const float4*)&Wp[(size_t)(kb + kk) * Hn + c4 * 4];
        }
        __syncthreads();
        #pragma unroll
        for (int kk = 0; kk < 32; kk++) {
            float4 b = ws[kk][tx];
            #pragma unroll
            for (int r = 0; r < 2; r++) {
                float a = fs[r0 + r][kk];
                acc[r][0] += a * b.x; acc[r][1] += a * b.y;
                acc[r][2] += a * b.z; acc[r][3] += a * b.w;
            }
        }
        __syncthreads();
    }

    float4 bv = *(const float4*)&bp[tx * 4];
    #pragma unroll
    for (int r = 0; r < 2; r++) {
        float4 o = make_float4(acc[r][0] + bv.x, acc[r][1] + bv.y,
                               acc[r][2] + bv.z, acc[r][3] + bv.w);
        *(float4*)&g_h[(size_t)(i0 + r0 + r) * Hn + tx * 4] = o;
    }
}

// ====== fused eval: hn = adjB @ x; z = tanh([x,hn]@W1 + b1); k = z@W2 + b2
//   mode 0: acc = h + (DT/6)k;  htmp = h + (DT/2)k
//   mode 1: acc += (DT/3)k;     htmp = h + (DT/2)k
//   mode 2: acc += (DT/3)k;     htmp = h +  DT  k
//   mode 3: hout = acc + (DT/6)k      (hout = g_h, or d_out on last step)
// BM=8, 128 threads, grid=512
__global__ __launch_bounds__(128) void eval_kernel(
        int x_is_htmp, int mode, float* __restrict__ dout, int to_dout,
        const float* __restrict__ W1, const float* __restrict__ b1,
        const float* __restrict__ W2, const float* __restrict__ b2)
{
    const float* __restrict__ x = x_is_htmp ? g_htmp : g_h;
    __shared__ __align__(16) float4 xs[32][32];      // 16KB: x j-tile
    __shared__            float adjS[8][32];         // 1KB
    __shared__ __align__(16) float xsh [8 * 128];    // 4KB
    __shared__ __align__(16) float hnsh[8 * 128];    // 4KB
    __shared__ __align__(16) float zsh [8 * 128];    // 4KB

    int t  = threadIdx.x;
    int tx = t & 31, ty = t >> 5;
    int i0 = blockIdx.x * 8;
    int r0 = ty * 2;                        // 2 rows per warp

    // ---------- phase A: banded matvec into hnsh ----------
    float acc[2][4] = {};

    for (int cb = 0; cb < NJT; cb++) {      // j in [i0-128, i0+160)
        int jbase = i0 - HBW + cb * 32;
        #pragma unroll
        for (int l = 0; l < 8; l++) {       // x tile: 32 rows x 128 cols
            int lin = t + l * 128;
            int jj = lin >> 5, c4 = lin & 31;
            int j = jbase + jj;
            float4 v = make_float4(0.f, 0.f, 0.f, 0.f);
            if (j >= 0 && j < Bn)
                v = *(const float4*)&x[(size_t)j * Hn + c4 * 4];
            xs[jj][c4] = v;
        }
        #pragma unroll
        for (int l = 0; l < 2; l++) {       // adj tile 8x32
            int lin = t + l * 128;
            int r = lin >> 5, jj = lin & 31;
            int off = cb * 32 + jj - r;     // = j - i + HBW
            int j = jbase + jj;
            float v = 0.f;
            if (off >= 0 && off < BAND && j >= 0 && j < Bn)
                v = g_adj[(size_t)(i0 + r) * BAND + off];
            adjS[r][jj] = v;
        }
        __syncthreads();
        #pragma unroll
        for (int kk = 0; kk < 32; kk++) {
            float4 b = xs[kk][tx];
            #pragma unroll
            for (int r = 0; r < 2; r++) {
                float a = adjS[r0 + r][kk];
                acc[r][0] += a * b.x; acc[r][1] += a * b.y;
                acc[r][2] += a * b.z; acc[r][3] += a * b.w;
            }
        }
        __syncthreads();
    }

    #pragma unroll
    for (int r = 0; r < 2; r++)
        *(float4*)&hnsh[(r0 + r) * 128 + tx * 4] =
            make_float4(acc[r][0], acc[r][1], acc[r][2], acc[r][3]);
    // stage x rows of this tile: 8 rows x 32 float4 = 256 -> 2 per thread
    {
        int lin = t;
        ((float4*)xsh)[lin] = *(const float4*)&x[(size_t)(i0 + (lin >> 5)) * Hn + (lin & 31) * 4];
        lin = t + 128;
        ((float4*)xsh)[lin] = *(const float4*)&x[(size_t)(i0 + (lin >> 5)) * Hn + (lin & 31) * 4];
    }
    __syncthreads();

    // ---------- phase B: layer 1  z = tanh([x,hn] @ W1 + b1) ----------
    float4 b1v = *(const float4*)&b1[tx * 4];
    float az[2][4];
    #pragma unroll
    for (int r = 0; r < 2; r++) {
        az[r][0] = b1v.x; az[r][1] = b1v.y; az[r][2] = b1v.z; az[r][3] = b1v.w;
    }
    #pragma unroll 8
    for (int kk = 0; kk < Hn; kk++) {
        float4 wt = *(const float4*)&W1[(size_t) kk       * Hn + tx * 4];
        float4 wb = *(const float4*)&W1[(size_t)(Hn + kk) * Hn + tx * 4];
        #pragma unroll
        for (int r = 0; r < 2; r++) {
            float xv = xsh [(r0 + r) * 128 + kk];
            float hv = hnsh[(r0 + r) * 128 + kk];
            az[r][0] += xv * wt.x + hv * wb.x;
            az[r][1] += xv * wt.y + hv * wb.y;
            az[r][2] += xv * wt.z + hv * wb.z;
            az[r][3] += xv * wt.w + hv * wb.w;
        }
    }
    #pragma unroll
    for (int r = 0; r < 2; r++)
        *(float4*)&zsh[(r0 + r) * 128 + tx * 4] =
            make_float4(tanhf(az[r][0]), tanhf(az[r][1]),
                        tanhf(az[r][2]), tanhf(az[r][3]));
    __syncthreads();

    // ---------- phase B: layer 2  k = z @ W2 + b2 ----------
    float4 b2v = *(const float4*)&b2[tx * 4];
    float ak[2][4];
    #pragma unroll
    for (int r = 0; r < 2; r++) {
        ak[r][0] = b2v.x; ak[r][1] = b2v.y; ak[r][2] = b2v.z; ak[r][3] = b2v.w;
    }
    #pragma unroll 8
    for (int kk = 0; kk < Hn; kk++) {
        float4 w2 = *(const float4*)&W2[(size_t)kk * Hn + tx * 4];
        #pragma unroll
        for (int r = 0; r < 2; r++) {
            float zv = zsh[(r0 + r) * 128 + kk];
            ak[r][0] += zv * w2.x; ak[r][1] += zv * w2.y;
            ak[r][2] += zv * w2.z; ak[r][3] += zv * w2.w;
        }
    }

    // ---------- fused RK4 epilogue ----------
    const float cA6 = DT / 6.0f, cA3 = DT / 3.0f, cH2 = DT * 0.5f;
    #pragma unroll
    for (int r = 0; r < 2; r++) {
        size_t g = (size_t)(i0 + r0 + r) * Hn + tx * 4;
        float4 k = make_float4(ak[r][0], ak[r][1], ak[r][2], ak[r][3]);
        if (mode == 0) {
            float4 hv = *(const float4*)&g_h[g];
            *(float4*)&g_acc[g]  = make_float4(hv.x + cA6*k.x, hv.y + cA6*k.y,
                                               hv.z + cA6*k.z, hv.w + cA6*k.w);
            *(float4*)&g_htmp[g] = make_float4(hv.x + cH2*k.x, hv.y + cH2*k.y,
                                               hv.z + cH2*k.z, hv.w + cH2*k.w);
        } else if (mode == 3) {
            float4 av = *(const float4*)&g_acc[g];
            float4 o = make_float4(av.x + cA6*k.x, av.y + cA6*k.y,
                                   av.z + cA6*k.z, av.w + cA6*k.w);
            if (to_dout) *(float4*)&dout[g] = o;
            else         *(float4*)&g_h[g]  = o;
        } else {
            float ct = (mode == 2) ? DT : cH2;
            float4 av = *(const float4*)&g_acc[g];
            *(float4*)&g_acc[g] = make_float4(av.x + cA3*k.x, av.y + cA3*k.y,
                                              av.z + cA3*k.z, av.w + cA3*k.w);
            float4 hv = *(const float4*)&g_h[g];
            *(float4*)&g_htmp[g] = make_float4(hv.x + ct*k.x, hv.y + ct*k.y,
                                               hv.z + ct*k.z, hv.w + ct*k.w);
        }
    }
}

// ================= launch =================
extern "C" void kernel_launch(void* const* d_in, const int* in_sizes, int n_in,
                              void* d_out, int out_size)
{
    const float* features = (const float*)d_in[0];
    const int*   spk      = (const int*)  d_in[1];
    const float* mm       = (const float*)d_in[2];
    const float* Wp       = (const float*)d_in[3];
    const float* bp       = (const float*)d_in[4];
    const float* W1       = (const float*)d_in[5];
    const float* b1       = (const float*)d_in[6];
    const float* W2       = (const float*)d_in[7];
    const float* b2       = (const float*)d_in[8];
    float* out = (float*)d_out;

    build_adj_kernel<<<Bn, 256>>>(spk, mm);
    proj_kernel<<<Bn/8, 128>>>(features, Wp, bp);

    for (int s = 0; s < 4; s++) {
        for (int e = 0; e < 4; e++) {
            eval_kernel<<<Bn/8, 128>>>(e > 0 ? 1 : 0, e, out,
                                       (s == 3 && e == 3) ? 1 : 0,
                                       W1, b1, W2, b2);
        }
    }
}